// round 15
// baseline (speedup 1.0000x reference)
#include <cuda_runtime.h>

#define BB 32
#define HB 16    // batches per half
#define CC 256
#define TT 4096
#define NH 8
#define DH 64
#define DK 512   // NH*DH

typedef unsigned long long u64;

// Scratch (allocation-free per harness rules)
__device__ float g_qW[BB * NH * CC];        // scale-folded q @ Wkv_k
__device__ float g_pl[2][BB * NH * TT];     // partial logits, 2 c-halves
__device__ float g_xp[2][BB * NH * CC];     // xattn partials (unnormalized), 2 j-halves
__device__ float g_es[2][BB * NH];          // exp sums per j-half
__device__ float g_oh[BB * DK];             // v-projection intermediate

// ---- packed f32x2 helpers ----
__device__ __forceinline__ u64 pk(float a, float b) {
    u64 v; asm("mov.b64 %0,{%1,%2};" : "=l"(v) : "f"(a), "f"(b)); return v;
}
__device__ __forceinline__ float2 upk(u64 v) {
    float2 f; asm("mov.b64 {%0,%1},%2;" : "=f"(f.x), "=f"(f.y) : "l"(v)); return f;
}
__device__ __forceinline__ void ffma2(u64& d, u64 a, u64 b) {
    asm("fma.rn.f32x2 %0,%1,%2,%0;" : "+l"(d) : "l"(a), "l"(b));
}

// ---------------------------------------------------------------------------
// Kernel A: per (n,b): q = query@Wq.T + bq ; qW[b,n,c] = scale * q·Wkv_k[:,c]
// grid = (8 n, 32 b), 256 threads
// ---------------------------------------------------------------------------
__global__ void k_prep(const float* __restrict__ query,
                       const float* __restrict__ Wq,
                       const float* __restrict__ bq,
                       const float* __restrict__ Wkv) {
    const int n = blockIdx.x, b = blockIdx.y;
    const int tid = threadIdx.x, wid = tid >> 5, lane = tid & 31;
    __shared__ float qin[CC];
    __shared__ float qs[DH];

    qin[tid] = query[b * CC + tid];
    __syncthreads();

    const float4* qv = (const float4*)qin;
    for (int d = wid; d < DH; d += 8) {
        const float4* wr = (const float4*)(Wq + (size_t)(n * DH + d) * CC);
        float s = 0.f;
#pragma unroll
        for (int i = 0; i < 2; ++i) {
            const float4 w = wr[lane + i * 32];
            const float4 q4 = qv[lane + i * 32];
            s += w.x * q4.x + w.y * q4.y + w.z * q4.z + w.w * q4.w;
        }
#pragma unroll
        for (int o = 16; o; o >>= 1) s += __shfl_xor_sync(~0u, s, o);
        if (!lane) qs[d] = s + bq[n * DH + d];
    }
    __syncthreads();

    const float* wbase = Wkv + (size_t)(n * DH) * CC + tid;
    float s = 0.f;
#pragma unroll 8
    for (int d = 0; d < DH; ++d) s += qs[d] * wbase[(size_t)d * CC];
    g_qW[(b * NH + n) * CC + tid] = s * 0.125f;  // 1/sqrt(64)
}

// ---------------------------------------------------------------------------
// Kernel B: partial logits for ONE batch half (16 b). No __ldcs — x must
// remain L2-resident for the following xattn half.
// grid = (8 j-tiles of 512, 2 ch, 16 b) = 256 blocks, 128 threads.
// ---------------------------------------------------------------------------
__global__ void __launch_bounds__(128) k_logits(const float* __restrict__ x,
                                                int b0) {
    const int b = b0 + blockIdx.z;
    const int ch = blockIdx.y;
    const int jq = blockIdx.x * 128 + threadIdx.x;   // 16B-unit index into j

    __shared__ u64 qw2[128][NH];                     // packed {w,w}, 8 KB
    for (int i = threadIdx.x; i < 128 * NH; i += 128) {
        const int c = i >> 3, n = i & 7;
        const float w = g_qW[(b * NH + n) * CC + ch * 128 + c];
        qw2[c][n] = pk(w, w);
    }
    __syncthreads();

    u64 acc2[NH][2];
#pragma unroll
    for (int n = 0; n < NH; ++n) { acc2[n][0] = 0ull; acc2[n][1] = 0ull; }

    const ulonglong2* xp =
        (const ulonglong2*)(x + ((size_t)b * CC + ch * 128) * TT) + jq;
#pragma unroll 8
    for (int c = 0; c < 128; ++c) {
        const ulonglong2 xv = xp[(size_t)c * (TT / 4)];
#pragma unroll
        for (int n = 0; n < NH; ++n) {
            const u64 w = qw2[c][n];
            ffma2(acc2[n][0], w, xv.x);
            ffma2(acc2[n][1], w, xv.y);
        }
    }

#pragma unroll
    for (int n = 0; n < NH; ++n) {
        const float2 lo = upk(acc2[n][0]);
        const float2 hi = upk(acc2[n][1]);
        ((float4*)(g_pl[ch] + (size_t)(b * NH + n) * TT))[jq] =
            make_float4(lo.x, lo.y, hi.x, hi.y);
    }
}

// ---------------------------------------------------------------------------
// Kernel D: xattn with inline softmax (exp(p0+p1), no max; |logit| < 2),
// for ONE batch half. x re-read should hit L2 (left warm by k_logits).
// grid = (8 c-tiles of 32, 2 jh, 16 b) = 256 blocks, 256 threads.
// ---------------------------------------------------------------------------
__global__ void __launch_bounds__(256, 2) k_xattn(const float* __restrict__ x,
                                                  int b0) {
    const int b = b0 + blockIdx.z;
    const int jh = blockIdx.y;
    const int cbase = blockIdx.x * 32 + (threadIdx.x >> 5) * 4;
    const int tid = threadIdx.x;
    const int lane = tid & 31;
    const int wid = tid >> 5;

    __shared__ float4 attn_s[NH][256];  // one 1024-j chunk of exp(l), 32 KB
    __shared__ float sred[NH][9];

    float acc[NH][4];
#pragma unroll
    for (int n = 0; n < NH; ++n)
#pragma unroll
        for (int cc = 0; cc < 4; ++cc) acc[n][cc] = 0.f;

    float sn[NH];
#pragma unroll
    for (int n = 0; n < NH; ++n) sn[n] = 0.f;

    const float4* p0 = (const float4*)(g_pl[0] + (size_t)b * NH * TT);
    const float4* p1 = (const float4*)(g_pl[1] + (size_t)b * NH * TT);

    for (int chunk = 0; chunk < 2; ++chunk) {
        const int jq0 = jh * 512 + chunk * 256;
        __syncthreads();
#pragma unroll
        for (int ii = 0; ii < NH; ++ii) {
            const int q = tid & 255;
            const size_t gi = (size_t)ii * (TT / 4) + jq0 + q;
            const float4 a = p0[gi];
            const float4 c = p1[gi];
            float4 e;
            e.x = __expf(a.x + c.x); e.y = __expf(a.y + c.y);
            e.z = __expf(a.z + c.z); e.w = __expf(a.w + c.w);
            attn_s[ii][q] = e;
            sn[ii] += e.x + e.y + e.z + e.w;
        }
        __syncthreads();

        const float4* xp = (const float4*)(x + (size_t)b * CC * TT) + jq0;
#pragma unroll
        for (int step = 0; step < 8; step += 4) {
            float4 xv[4][4];
#pragma unroll
            for (int u = 0; u < 4; ++u) {
                const int q = lane + (step + u) * 32;
#pragma unroll
                for (int cc = 0; cc < 4; ++cc)
                    xv[u][cc] = __ldcs(&xp[(size_t)(cbase + cc) * (TT / 4) + q]);
            }
#pragma unroll
            for (int u = 0; u < 4; ++u) {
                const int q = lane + (step + u) * 32;
#pragma unroll
                for (int n = 0; n < NH; ++n) {
                    const float4 a = attn_s[n][q];
#pragma unroll
                    for (int cc = 0; cc < 4; ++cc)
                        acc[n][cc] += a.x * xv[u][cc].x + a.y * xv[u][cc].y +
                                      a.z * xv[u][cc].z + a.w * xv[u][cc].w;
                }
            }
        }
    }

    // per-head exp sums over this block's 1024 j (counted once per chunk)
#pragma unroll
    for (int n = 0; n < NH; ++n) {
        float s = sn[n];
#pragma unroll
        for (int o = 16; o; o >>= 1) s += __shfl_xor_sync(~0u, s, o);
        if (!lane) sred[n][wid] = s;
    }

#pragma unroll
    for (int n = 0; n < NH; ++n)
#pragma unroll
        for (int cc = 0; cc < 4; ++cc) {
            float v = acc[n][cc];
#pragma unroll
            for (int o = 16; o; o >>= 1) v += __shfl_xor_sync(~0u, v, o);
            if (lane == 0) g_xp[jh][(size_t)(b * NH + n) * CC + cbase + cc] = v;
        }

    __syncthreads();
    if (blockIdx.x == 0 && tid < NH) {
        float s = sred[tid][0];
#pragma unroll
        for (int w = 1; w < 8; ++w) s += sred[tid][w];
        g_es[jh][b * NH + tid] = s;
    }
}

// ---------------------------------------------------------------------------
// Kernel E1: oh[b,nd] = Wkv_v[nd]·((xp0+xp1)/(s0+s1))[b,n] + bkv_v[nd]
// grid = (16 nd-tiles of 32, 4 b-groups of 8), 256 threads, thread-per-output.
// ---------------------------------------------------------------------------
__global__ void __launch_bounds__(256) k_out1(const float* __restrict__ Wkv,
                                              const float* __restrict__ bkv) {
    const int ndt = blockIdx.x, bg = blockIdx.y;
    const int n = ndt >> 1;
    const int tid = threadIdx.x;
    __shared__ float ws[32][260];
    __shared__ float xs[8][260];
    __shared__ float inv_s[8];

    if (tid < 8) {
        const int b = bg * 8 + tid;
        inv_s[tid] = 1.f / (g_es[0][b * NH + n] + g_es[1][b * NH + n]);
    }

    const float4* wsrc = (const float4*)(Wkv + (size_t)(DK + ndt * 32) * CC);
    for (int i = tid; i < 32 * 64; i += 256)
        *(float4*)&ws[i >> 6][(i & 63) * 4] = wsrc[i];
    for (int i = tid; i < 8 * 64; i += 256) {
        const int bl = i >> 6, c4 = i & 63;
        const size_t gi = ((size_t)((bg * 8 + bl) * NH + n)) * CC + c4 * 4;
        const float4 a = *(const float4*)&g_xp[0][gi];
        const float4 c = *(const float4*)&g_xp[1][gi];
        *(float4*)&xs[bl][c4 * 4] =
            make_float4(a.x + c.x, a.y + c.y, a.z + c.z, a.w + c.w);
    }
    __syncthreads();

    const int ndl = tid >> 3, bl = tid & 7;
    float acc = 0.f;
#pragma unroll 8
    for (int c4 = 0; c4 < 64; ++c4) {
        const float4 w = *(const float4*)&ws[ndl][c4 * 4];
        const float4 v = *(const float4*)&xs[bl][c4 * 4];
        acc += w.x * v.x + w.y * v.y + w.z * v.z + w.w * v.w;
    }
    const int nd = ndt * 32 + ndl;
    g_oh[(bg * 8 + bl) * DK + nd] = acc * inv_s[bl] + bkv[DK + nd];
}

// ---------------------------------------------------------------------------
// Kernel E2: y[b,o] = relu(oh[b]·Wfc[o] + bfc[o])
// grid = (8 o-tiles of 32, 4 b-groups of 8), 256 threads, thread-per-output.
// ---------------------------------------------------------------------------
__global__ void __launch_bounds__(256) k_out2(const float* __restrict__ Wfc,
                                              const float* __restrict__ bfc,
                                              float* __restrict__ out) {
    const int ot = blockIdx.x, bg = blockIdx.y;
    const int tid = threadIdx.x;
    __shared__ float ws[32][516];
    __shared__ float xs[8][516];

    const float4* wsrc = (const float4*)(Wfc + (size_t)(ot * 32) * DK);
    for (int i = tid; i < 32 * 128; i += 256)
        *(float4*)&ws[i >> 7][(i & 127) * 4] = wsrc[i];
    for (int i = tid; i < 8 * 128; i += 256) {
        const int bl = i >> 7, k4 = i & 127;
        *(float4*)&xs[bl][k4 * 4] =
            *(const float4*)&g_oh[(bg * 8 + bl) * DK + k4 * 4];
    }
    __syncthreads();

    const int ol = tid >> 3, bl = tid & 7;
    float acc = 0.f;
#pragma unroll 8
    for (int k4 = 0; k4 < 128; ++k4) {
        const float4 w = *(const float4*)&ws[ol][k4 * 4];
        const float4 v = *(const float4*)&xs[bl][k4 * 4];
        acc += w.x * v.x + w.y * v.y + w.z * v.z + w.w * v.w;
    }
    const int o = ot * 32 + ol;
    out[(bg * 8 + bl) * CC + o] = fmaxf(acc + bfc[o], 0.f);
}

// ---------------------------------------------------------------------------
extern "C" void kernel_launch(void* const* d_in, const int* in_sizes, int n_in,
                              void* d_out, int out_size) {
    const float* x     = (const float*)d_in[0];  // (32,256,64,64)
    const float* query = (const float*)d_in[1];  // (32,256)
    const float* Wkv   = (const float*)d_in[2];  // (1024,256)
    const float* bkv   = (const float*)d_in[3];  // (1024)
    const float* Wq    = (const float*)d_in[4];  // (512,256)
    const float* bq    = (const float*)d_in[5];  // (512)
    const float* Wfc   = (const float*)d_in[6];  // (256,512)
    const float* bfc   = (const float*)d_in[7];  // (256)
    float* out = (float*)d_out;                  // (32,256)

    k_prep<<<dim3(NH, BB), 256>>>(query, Wq, bq, Wkv);
    // Batch-halved pipeline: each half's x (64 MB) stays L2-resident
    // between its logits pass and its xattn pass.
    k_logits<<<dim3(TT / 512, 2, HB), 128>>>(x, 0);
    k_xattn<<<dim3(CC / 32, 2, HB), 256>>>(x, 0);
    k_logits<<<dim3(TT / 512, 2, HB), 128>>>(x, HB);
    k_xattn<<<dim3(CC / 32, 2, HB), 256>>>(x, HB);
    k_out1<<<dim3(16, 4), 256>>>(Wkv, bkv);
    k_out2<<<dim3(NH, 4), 256>>>(Wfc, bfc, out);
}

// round 16
// speedup vs baseline: 1.1430x; 1.1430x over previous
#include <cuda_runtime.h>

#define BB 32
#define CC 256
#define TT 4096
#define NH 8
#define DH 64
#define DK 512   // NH*DH

typedef unsigned long long u64;

// Scratch (allocation-free per harness rules)
__device__ float g_qW[BB * NH * CC];        // scale-folded q @ Wkv_k
__device__ float g_pl[BB * NH * TT];        // logits (single pass)
__device__ float g_xp[2][BB * NH * CC];     // xattn partials (unnormalized), 2 j-halves
__device__ float g_es[2][BB * NH];          // exp sums per j-half
__device__ float g_oh[BB * DK];             // v-projection intermediate

// ---- packed f32x2 helpers ----
__device__ __forceinline__ u64 pk(float a, float b) {
    u64 v; asm("mov.b64 %0,{%1,%2};" : "=l"(v) : "f"(a), "f"(b)); return v;
}
__device__ __forceinline__ float2 upk(u64 v) {
    float2 f; asm("mov.b64 {%0,%1},%2;" : "=f"(f.x), "=f"(f.y) : "l"(v)); return f;
}
__device__ __forceinline__ void ffma2(u64& d, u64 a, u64 b) {
    asm("fma.rn.f32x2 %0,%1,%2,%0;" : "+l"(d) : "l"(a), "l"(b));
}

// ---------------------------------------------------------------------------
// Kernel A: per (n,b): q = query@Wq.T + bq ; qW[b,n,c] = scale * q·Wkv_k[:,c]
// grid = (8 n, 32 b), 256 threads
// ---------------------------------------------------------------------------
__global__ void k_prep(const float* __restrict__ query,
                       const float* __restrict__ Wq,
                       const float* __restrict__ bq,
                       const float* __restrict__ Wkv) {
    const int n = blockIdx.x, b = blockIdx.y;
    const int tid = threadIdx.x, wid = tid >> 5, lane = tid & 31;
    __shared__ float qin[CC];
    __shared__ float qs[DH];

    qin[tid] = query[b * CC + tid];
    __syncthreads();

    const float4* qv = (const float4*)qin;
    for (int d = wid; d < DH; d += 8) {
        const float4* wr = (const float4*)(Wq + (size_t)(n * DH + d) * CC);
        float s = 0.f;
#pragma unroll
        for (int i = 0; i < 2; ++i) {
            const float4 w = wr[lane + i * 32];
            const float4 q4 = qv[lane + i * 32];
            s += w.x * q4.x + w.y * q4.y + w.z * q4.z + w.w * q4.w;
        }
#pragma unroll
        for (int o = 16; o; o >>= 1) s += __shfl_xor_sync(~0u, s, o);
        if (!lane) qs[d] = s + bq[n * DH + d];
    }
    __syncthreads();

    const float* wbase = Wkv + (size_t)(n * DH) * CC + tid;
    float s = 0.f;
#pragma unroll 8
    for (int d = 0; d < DH; ++d) s += qs[d] * wbase[(size_t)d * CC];
    g_qW[(b * NH + n) * CC + tid] = s * 0.125f;  // 1/sqrt(64)
}

// ---------------------------------------------------------------------------
// Kernel B: full logits in ONE c-pass (no c-split, no partial-sum traffic).
// grid = (4 j-tiles of 1024, 32 b) = 128 blocks, 256 threads. FFMA2 math.
// ---------------------------------------------------------------------------
__global__ void __launch_bounds__(256) k_logits(const float* __restrict__ x) {
    const int b = blockIdx.y;
    const int jq = blockIdx.x * 256 + threadIdx.x;   // 16B-unit index into j

    __shared__ u64 qw2[CC][NH];                      // packed {w,w}, 16 KB
    for (int i = threadIdx.x; i < CC * NH; i += 256) {
        const int c = i >> 3, n = i & 7;
        qw2[c][n] = pk(g_qW[(b * NH + n) * CC + c], g_qW[(b * NH + n) * CC + c]);
    }
    __syncthreads();

    u64 acc2[NH][2];
#pragma unroll
    for (int n = 0; n < NH; ++n) { acc2[n][0] = 0ull; acc2[n][1] = 0ull; }

    const ulonglong2* xp = (const ulonglong2*)(x + (size_t)b * CC * TT) + jq;
#pragma unroll 8
    for (int c = 0; c < CC; ++c) {
        const ulonglong2 xv = __ldcs(&xp[(size_t)c * (TT / 4)]);
#pragma unroll
        for (int n = 0; n < NH; ++n) {
            const u64 w = qw2[c][n];
            ffma2(acc2[n][0], w, xv.x);
            ffma2(acc2[n][1], w, xv.y);
        }
    }

#pragma unroll
    for (int n = 0; n < NH; ++n) {
        const float2 lo = upk(acc2[n][0]);
        const float2 hi = upk(acc2[n][1]);
        ((float4*)(g_pl + (size_t)(b * NH + n) * TT))[jq] =
            make_float4(lo.x, lo.y, hi.x, hi.y);
    }
}

// ---------------------------------------------------------------------------
// Kernel D: xattn with inline softmax (exp(l), no max; |logit| < 2).
// grid = (8 c-tiles of 32, 2 jh, 32 b), 256 threads = 8 warps, warp owns 4 c.
// ---------------------------------------------------------------------------
__global__ void __launch_bounds__(256, 2) k_xattn(const float* __restrict__ x) {
    const int b = blockIdx.z;
    const int jh = blockIdx.y;
    const int cbase = blockIdx.x * 32 + (threadIdx.x >> 5) * 4;
    const int tid = threadIdx.x;
    const int lane = tid & 31;
    const int wid = tid >> 5;

    __shared__ float4 attn_s[NH][256];  // one 1024-j chunk of exp(l), 32 KB
    __shared__ float sred[NH][9];

    float acc[NH][4];
#pragma unroll
    for (int n = 0; n < NH; ++n)
#pragma unroll
        for (int cc = 0; cc < 4; ++cc) acc[n][cc] = 0.f;

    float sn[NH];
#pragma unroll
    for (int n = 0; n < NH; ++n) sn[n] = 0.f;

    const float4* pl = (const float4*)(g_pl + (size_t)b * NH * TT);

    for (int chunk = 0; chunk < 2; ++chunk) {
        const int jq0 = jh * 512 + chunk * 256;
        __syncthreads();
#pragma unroll
        for (int ii = 0; ii < NH; ++ii) {
            const int q = tid & 255;
            const float4 a = pl[(size_t)ii * (TT / 4) + jq0 + q];
            float4 e;
            e.x = __expf(a.x); e.y = __expf(a.y);
            e.z = __expf(a.z); e.w = __expf(a.w);
            attn_s[ii][q] = e;
            sn[ii] += e.x + e.y + e.z + e.w;
        }
        __syncthreads();

        const float4* xp = (const float4*)(x + (size_t)b * CC * TT) + jq0;
#pragma unroll
        for (int step = 0; step < 8; step += 4) {
            float4 xv[4][4];
#pragma unroll
            for (int u = 0; u < 4; ++u) {
                const int q = lane + (step + u) * 32;
#pragma unroll
                for (int cc = 0; cc < 4; ++cc)
                    xv[u][cc] = __ldcs(&xp[(size_t)(cbase + cc) * (TT / 4) + q]);
            }
#pragma unroll
            for (int u = 0; u < 4; ++u) {
                const int q = lane + (step + u) * 32;
#pragma unroll
                for (int n = 0; n < NH; ++n) {
                    const float4 a = attn_s[n][q];
#pragma unroll
                    for (int cc = 0; cc < 4; ++cc)
                        acc[n][cc] += a.x * xv[u][cc].x + a.y * xv[u][cc].y +
                                      a.z * xv[u][cc].z + a.w * xv[u][cc].w;
                }
            }
        }
    }

    // per-head exp sums over this block's 1024 j
#pragma unroll
    for (int n = 0; n < NH; ++n) {
        float s = sn[n];
#pragma unroll
        for (int o = 16; o; o >>= 1) s += __shfl_xor_sync(~0u, s, o);
        if (!lane) sred[n][wid] = s;
    }

#pragma unroll
    for (int n = 0; n < NH; ++n)
#pragma unroll
        for (int cc = 0; cc < 4; ++cc) {
            float v = acc[n][cc];
#pragma unroll
            for (int o = 16; o; o >>= 1) v += __shfl_xor_sync(~0u, v, o);
            if (lane == 0) g_xp[jh][(size_t)(b * NH + n) * CC + cbase + cc] = v;
        }

    __syncthreads();
    if (blockIdx.x == 0 && tid < NH) {
        float s = sred[tid][0];
#pragma unroll
        for (int w = 1; w < 8; ++w) s += sred[tid][w];
        g_es[jh][b * NH + tid] = s;
    }
}

// ---------------------------------------------------------------------------
// Kernel E1: oh[b,nd] = Wkv_v[nd]·((xp0+xp1)/(s0+s1))[b,n] + bkv_v[nd]
// grid = (16 nd-tiles of 32, 4 b-groups of 8), 256 threads, thread-per-output.
// ---------------------------------------------------------------------------
__global__ void __launch_bounds__(256) k_out1(const float* __restrict__ Wkv,
                                              const float* __restrict__ bkv) {
    const int ndt = blockIdx.x, bg = blockIdx.y;
    const int n = ndt >> 1;
    const int tid = threadIdx.x;
    __shared__ float ws[32][260];
    __shared__ float xs[8][260];
    __shared__ float inv_s[8];

    if (tid < 8) {
        const int b = bg * 8 + tid;
        inv_s[tid] = 1.f / (g_es[0][b * NH + n] + g_es[1][b * NH + n]);
    }

    const float4* wsrc = (const float4*)(Wkv + (size_t)(DK + ndt * 32) * CC);
    for (int i = tid; i < 32 * 64; i += 256)
        *(float4*)&ws[i >> 6][(i & 63) * 4] = wsrc[i];
    for (int i = tid; i < 8 * 64; i += 256) {
        const int bl = i >> 6, c4 = i & 63;
        const size_t gi = ((size_t)((bg * 8 + bl) * NH + n)) * CC + c4 * 4;
        const float4 a = *(const float4*)&g_xp[0][gi];
        const float4 c = *(const float4*)&g_xp[1][gi];
        *(float4*)&xs[bl][c4 * 4] =
            make_float4(a.x + c.x, a.y + c.y, a.z + c.z, a.w + c.w);
    }
    __syncthreads();

    const int ndl = tid >> 3, bl = tid & 7;
    float acc = 0.f;
#pragma unroll 8
    for (int c4 = 0; c4 < 64; ++c4) {
        const float4 w = *(const float4*)&ws[ndl][c4 * 4];
        const float4 v = *(const float4*)&xs[bl][c4 * 4];
        acc += w.x * v.x + w.y * v.y + w.z * v.z + w.w * v.w;
    }
    const int nd = ndt * 32 + ndl;
    g_oh[(bg * 8 + bl) * DK + nd] = acc * inv_s[bl] + bkv[DK + nd];
}

// ---------------------------------------------------------------------------
// Kernel E2: y[b,o] = relu(oh[b]·Wfc[o] + bfc[o])
// grid = (8 o-tiles of 32, 4 b-groups of 8), 256 threads, thread-per-output.
// ---------------------------------------------------------------------------
__global__ void __launch_bounds__(256) k_out2(const float* __restrict__ Wfc,
                                              const float* __restrict__ bfc,
                                              float* __restrict__ out) {
    const int ot = blockIdx.x, bg = blockIdx.y;
    const int tid = threadIdx.x;
    __shared__ float ws[32][516];
    __shared__ float xs[8][516];

    const float4* wsrc = (const float4*)(Wfc + (size_t)(ot * 32) * DK);
    for (int i = tid; i < 32 * 128; i += 256)
        *(float4*)&ws[i >> 7][(i & 127) * 4] = wsrc[i];
    for (int i = tid; i < 8 * 128; i += 256) {
        const int bl = i >> 7, k4 = i & 127;
        *(float4*)&xs[bl][k4 * 4] =
            *(const float4*)&g_oh[(bg * 8 + bl) * DK + k4 * 4];
    }
    __syncthreads();

    const int ol = tid >> 3, bl = tid & 7;
    float acc = 0.f;
#pragma unroll 8
    for (int k4 = 0; k4 < 128; ++k4) {
        const float4 w = *(const float4*)&ws[ol][k4 * 4];
        const float4 v = *(const float4*)&xs[bl][k4 * 4];
        acc += w.x * v.x + w.y * v.y + w.z * v.z + w.w * v.w;
    }
    const int o = ot * 32 + ol;
    out[(bg * 8 + bl) * CC + o] = fmaxf(acc + bfc[o], 0.f);
}

// ---------------------------------------------------------------------------
extern "C" void kernel_launch(void* const* d_in, const int* in_sizes, int n_in,
                              void* d_out, int out_size) {
    const float* x     = (const float*)d_in[0];  // (32,256,64,64)
    const float* query = (const float*)d_in[1];  // (32,256)
    const float* Wkv   = (const float*)d_in[2];  // (1024,256)
    const float* bkv   = (const float*)d_in[3];  // (1024)
    const float* Wq    = (const float*)d_in[4];  // (512,256)
    const float* bq    = (const float*)d_in[5];  // (512)
    const float* Wfc   = (const float*)d_in[6];  // (256,512)
    const float* bfc   = (const float*)d_in[7];  // (256)
    float* out = (float*)d_out;                  // (32,256)

    k_prep<<<dim3(NH, BB), 256>>>(query, Wq, bq, Wkv);
    k_logits<<<dim3(TT / 1024, BB), 256>>>(x);
    k_xattn<<<dim3(CC / 32, 2, BB), 256>>>(x);
    k_out1<<<dim3(16, 4), 256>>>(Wkv, bkv);
    k_out2<<<dim3(NH, 4), 256>>>(Wfc, bfc, out);
}

// round 17
// speedup vs baseline: 1.5967x; 1.3970x over previous
#include <cuda_runtime.h>

#define BB 32
#define CC 256
#define TT 4096
#define NH 8
#define DH 64
#define DK 512   // NH*DH

typedef unsigned long long u64;

// Scratch (allocation-free per harness rules)
__device__ float g_qW[BB * NH * CC];        // scale-folded q @ Wkv_k
__device__ float g_pl[2][BB * NH * TT];     // partial logits, 2 c-halves
__device__ float g_xp[2][BB * NH * CC];     // xattn partials (unnormalized), 2 j-halves
__device__ float g_es[2][BB * NH];          // exp sums per j-half
__device__ float g_oh[BB * DK];             // v-projection intermediate

// ---- packed f32x2 helpers ----
__device__ __forceinline__ u64 pk(float a, float b) {
    u64 v; asm("mov.b64 %0,{%1,%2};" : "=l"(v) : "f"(a), "f"(b)); return v;
}
__device__ __forceinline__ float2 upk(u64 v) {
    float2 f; asm("mov.b64 {%0,%1},%2;" : "=f"(f.x), "=f"(f.y) : "l"(v)); return f;
}
__device__ __forceinline__ void ffma2(u64& d, u64 a, u64 b) {
    asm("fma.rn.f32x2 %0,%1,%2,%0;" : "+l"(d) : "l"(a), "l"(b));
}

// ---------------------------------------------------------------------------
// Kernel A: per (n,b): q = query@Wq.T + bq ; qW[b,n,c] = scale * q·Wkv_k[:,c]
// grid = (8 n, 32 b), 256 threads
// ---------------------------------------------------------------------------
__global__ void k_prep(const float* __restrict__ query,
                       const float* __restrict__ Wq,
                       const float* __restrict__ bq,
                       const float* __restrict__ Wkv) {
    const int n = blockIdx.x, b = blockIdx.y;
    const int tid = threadIdx.x, wid = tid >> 5, lane = tid & 31;
    __shared__ float qin[CC];
    __shared__ float qs[DH];

    qin[tid] = query[b * CC + tid];
    __syncthreads();

    const float4* qv = (const float4*)qin;
    for (int d = wid; d < DH; d += 8) {
        const float4* wr = (const float4*)(Wq + (size_t)(n * DH + d) * CC);
        float s = 0.f;
#pragma unroll
        for (int i = 0; i < 2; ++i) {
            const float4 w = wr[lane + i * 32];
            const float4 q4 = qv[lane + i * 32];
            s += w.x * q4.x + w.y * q4.y + w.z * q4.z + w.w * q4.w;
        }
#pragma unroll
        for (int o = 16; o; o >>= 1) s += __shfl_xor_sync(~0u, s, o);
        if (!lane) qs[d] = s + bq[n * DH + d];
    }
    __syncthreads();

    const float* wbase = Wkv + (size_t)(n * DH) * CC + tid;
    float s = 0.f;
#pragma unroll 8
    for (int d = 0; d < DH; ++d) s += qs[d] * wbase[(size_t)d * CC];
    g_qW[(b * NH + n) * CC + tid] = s * 0.125f;  // 1/sqrt(64)
}

// ---------------------------------------------------------------------------
// Kernel B: partial logits, c in halves; FFMA2 math. (R14 exact)
// grid = (4 j-tiles of 1024, 2 c-halves, 32 b) = 256 blocks, 256 threads.
// ---------------------------------------------------------------------------
__global__ void __launch_bounds__(256) k_logits(const float* __restrict__ x) {
    const int b = blockIdx.z;
    const int ch = blockIdx.y;
    const int jq = blockIdx.x * 256 + threadIdx.x;   // 16B-unit index into j

    __shared__ u64 qw2[128][NH];                     // packed {w,w}, 8 KB
    for (int i = threadIdx.x; i < 128 * NH; i += 256) {
        const int c = i >> 3, n = i & 7;
        const float w = g_qW[(b * NH + n) * CC + ch * 128 + c];
        qw2[c][n] = pk(w, w);
    }
    __syncthreads();

    u64 acc2[NH][2];
#pragma unroll
    for (int n = 0; n < NH; ++n) { acc2[n][0] = 0ull; acc2[n][1] = 0ull; }

    const ulonglong2* xp =
        (const ulonglong2*)(x + ((size_t)b * CC + ch * 128) * TT) + jq;
#pragma unroll 8
    for (int c = 0; c < 128; ++c) {
        const ulonglong2 xv = __ldcs(&xp[(size_t)c * (TT / 4)]);
#pragma unroll
        for (int n = 0; n < NH; ++n) {
            const u64 w = qw2[c][n];
            ffma2(acc2[n][0], w, xv.x);
            ffma2(acc2[n][1], w, xv.y);
        }
    }

#pragma unroll
    for (int n = 0; n < NH; ++n) {
        const float2 lo = upk(acc2[n][0]);
        const float2 hi = upk(acc2[n][1]);
        ((float4*)(g_pl[ch] + (size_t)(b * NH + n) * TT))[jq] =
            make_float4(lo.x, lo.y, hi.x, hi.y);
    }
}

// ---------------------------------------------------------------------------
// Kernel D: xattn with inline softmax (exp(p0+p1), no max; |logit| < 2).
// grid = (8 c-tiles of 32, 2 jh, 32 b) = 512 blocks, 256 threads. (R14 exact)
// ---------------------------------------------------------------------------
__global__ void __launch_bounds__(256, 2) k_xattn(const float* __restrict__ x) {
    const int b = blockIdx.z;
    const int jh = blockIdx.y;
    const int cbase = blockIdx.x * 32 + (threadIdx.x >> 5) * 4;
    const int tid = threadIdx.x;
    const int lane = tid & 31;
    const int wid = tid >> 5;

    __shared__ float4 attn_s[NH][256];  // one 1024-j chunk of exp(l), 32 KB
    __shared__ float sred[NH][9];

    float acc[NH][4];
#pragma unroll
    for (int n = 0; n < NH; ++n)
#pragma unroll
        for (int cc = 0; cc < 4; ++cc) acc[n][cc] = 0.f;

    float sn[NH];
#pragma unroll
    for (int n = 0; n < NH; ++n) sn[n] = 0.f;

    const float4* p0 = (const float4*)(g_pl[0] + (size_t)b * NH * TT);
    const float4* p1 = (const float4*)(g_pl[1] + (size_t)b * NH * TT);

    for (int chunk = 0; chunk < 2; ++chunk) {
        const int jq0 = jh * 512 + chunk * 256;
        __syncthreads();
#pragma unroll
        for (int ii = 0; ii < NH; ++ii) {
            const int q = tid & 255;
            const size_t gi = (size_t)ii * (TT / 4) + jq0 + q;
            const float4 a = p0[gi];
            const float4 c = p1[gi];
            float4 e;
            e.x = __expf(a.x + c.x); e.y = __expf(a.y + c.y);
            e.z = __expf(a.z + c.z); e.w = __expf(a.w + c.w);
            attn_s[ii][q] = e;
            sn[ii] += e.x + e.y + e.z + e.w;
        }
        __syncthreads();

        const float4* xp = (const float4*)(x + (size_t)b * CC * TT) + jq0;
#pragma unroll
        for (int step = 0; step < 8; step += 4) {
            float4 xv[4][4];
#pragma unroll
            for (int u = 0; u < 4; ++u) {
                const int q = lane + (step + u) * 32;
#pragma unroll
                for (int cc = 0; cc < 4; ++cc)
                    xv[u][cc] = __ldcs(&xp[(size_t)(cbase + cc) * (TT / 4) + q]);
            }
#pragma unroll
            for (int u = 0; u < 4; ++u) {
                const int q = lane + (step + u) * 32;
#pragma unroll
                for (int n = 0; n < NH; ++n) {
                    const float4 a = attn_s[n][q];
#pragma unroll
                    for (int cc = 0; cc < 4; ++cc)
                        acc[n][cc] += a.x * xv[u][cc].x + a.y * xv[u][cc].y +
                                      a.z * xv[u][cc].z + a.w * xv[u][cc].w;
                }
            }
        }
    }

#pragma unroll
    for (int n = 0; n < NH; ++n) {
        float s = sn[n];
#pragma unroll
        for (int o = 16; o; o >>= 1) s += __shfl_xor_sync(~0u, s, o);
        if (!lane) sred[n][wid] = s;
    }

#pragma unroll
    for (int n = 0; n < NH; ++n)
#pragma unroll
        for (int cc = 0; cc < 4; ++cc) {
            float v = acc[n][cc];
#pragma unroll
            for (int o = 16; o; o >>= 1) v += __shfl_xor_sync(~0u, v, o);
            if (lane == 0) g_xp[jh][(size_t)(b * NH + n) * CC + cbase + cc] = v;
        }

    __syncthreads();
    if (blockIdx.x == 0 && tid < NH) {
        float s = sred[tid][0];
#pragma unroll
        for (int w = 1; w < 8; ++w) s += sred[tid][w];
        g_es[jh][b * NH + tid] = s;
    }
}

// ---------------------------------------------------------------------------
// Kernel E1: oh[b,nd] = Wkv_v[nd]·((xp0+xp1)/(s0+s1))[b,n] + bkv_v[nd]
// Block = 8 nd x 8 b, 4 threads per output (64-c segments).
// grid = (64 nd-tiles, 4 b-groups) = 256 blocks, 256 threads.
// ---------------------------------------------------------------------------
__global__ void __launch_bounds__(256) k_out1(const float* __restrict__ Wkv,
                                              const float* __restrict__ bkv) {
    const int ndt = blockIdx.x, bg = blockIdx.y;
    const int n = ndt >> 3;                 // head of this 8-row nd tile
    const int tid = threadIdx.x;
    __shared__ float ws[8][260];
    __shared__ float xs[8][260];
    __shared__ float inv_s[8];

    if (tid < 8) {
        const int b = bg * 8 + tid;
        inv_s[tid] = 1.f / (g_es[0][b * NH + n] + g_es[1][b * NH + n]);
    }

    const float4* wsrc = (const float4*)(Wkv + (size_t)(DK + ndt * 8) * CC);
#pragma unroll
    for (int i = tid; i < 8 * 64; i += 256)
        *(float4*)&ws[i >> 6][(i & 63) * 4] = wsrc[i];
#pragma unroll
    for (int i = tid; i < 8 * 64; i += 256) {
        const int bl = i >> 6, c4 = i & 63;
        const size_t gi = ((size_t)((bg * 8 + bl) * NH + n)) * CC + c4 * 4;
        const float4 a = *(const float4*)&g_xp[0][gi];
        const float4 c = *(const float4*)&g_xp[1][gi];
        *(float4*)&xs[bl][c4 * 4] =
            make_float4(a.x + c.x, a.y + c.y, a.z + c.z, a.w + c.w);
    }
    __syncthreads();

    const int ndl = tid >> 5, bl = (tid >> 2) & 7, cseg = tid & 3;
    float acc = 0.f;
#pragma unroll 16
    for (int i = 0; i < 64; ++i) {
        const int c = 4 * i + cseg;
        acc += ws[ndl][c] * xs[bl][c];
    }
    acc += __shfl_xor_sync(~0u, acc, 1);
    acc += __shfl_xor_sync(~0u, acc, 2);
    if (cseg == 0) {
        const int nd = ndt * 8 + ndl;
        g_oh[(bg * 8 + bl) * DK + nd] = acc * inv_s[bl] + bkv[DK + nd];
    }
}

// ---------------------------------------------------------------------------
// Kernel E2: y[b,o] = relu(oh[b]·Wfc[o] + bfc[o])
// Block = 8 o x 8 b, 4 threads per output (128-k segments).
// grid = (32 o-tiles, 4 b-groups) = 128 blocks, 256 threads.
// ---------------------------------------------------------------------------
__global__ void __launch_bounds__(256) k_out2(const float* __restrict__ Wfc,
                                              const float* __restrict__ bfc,
                                              float* __restrict__ out) {
    const int ot = blockIdx.x, bg = blockIdx.y;
    const int tid = threadIdx.x;
    __shared__ float ws[8][516];
    __shared__ float xs[8][516];

    const float4* wsrc = (const float4*)(Wfc + (size_t)(ot * 8) * DK);
#pragma unroll
    for (int i = tid; i < 8 * 128; i += 256)
        *(float4*)&ws[i >> 7][(i & 127) * 4] = wsrc[i];
#pragma unroll
    for (int i = tid; i < 8 * 128; i += 256) {
        const int bl = i >> 7, k4 = i & 127;
        *(float4*)&xs[bl][k4 * 4] =
            *(const float4*)&g_oh[(bg * 8 + bl) * DK + k4 * 4];
    }
    __syncthreads();

    const int ol = tid >> 5, bl = (tid >> 2) & 7, kseg = tid & 3;
    float acc = 0.f;
#pragma unroll 16
    for (int i = 0; i < 128; ++i) {
        const int k = 4 * i + kseg;
        acc += ws[ol][k] * xs[bl][k];
    }
    acc += __shfl_xor_sync(~0u, acc, 1);
    acc += __shfl_xor_sync(~0u, acc, 2);
    if (kseg == 0) {
        const int o = ot * 8 + ol;
        out[(bg * 8 + bl) * CC + o] = fmaxf(acc + bfc[o], 0.f);
    }
}

// ---------------------------------------------------------------------------
extern "C" void kernel_launch(void* const* d_in, const int* in_sizes, int n_in,
                              void* d_out, int out_size) {
    const float* x     = (const float*)d_in[0];  // (32,256,64,64)
    const float* query = (const float*)d_in[1];  // (32,256)
    const float* Wkv   = (const float*)d_in[2];  // (1024,256)
    const float* bkv   = (const float*)d_in[3];  // (1024)
    const float* Wq    = (const float*)d_in[4];  // (512,256)
    const float* bq    = (const float*)d_in[5];  // (512)
    const float* Wfc   = (const float*)d_in[6];  // (256,512)
    const float* bfc   = (const float*)d_in[7];  // (256)
    float* out = (float*)d_out;                  // (32,256)

    k_prep<<<dim3(NH, BB), 256>>>(query, Wq, bq, Wkv);
    k_logits<<<dim3(TT / 1024, 2, BB), 256>>>(x);
    k_xattn<<<dim3(CC / 32, 2, BB), 256>>>(x);
    k_out1<<<dim3(64, 4), 256>>>(Wkv, bkv);
    k_out2<<<dim3(32, 4), 256>>>(Wfc, bfc, out);
}